// round 14
// baseline (speedup 1.0000x reference)
#include <cuda_runtime.h>
#include <cuda_bf16.h>
#include <cuda_fp16.h>
#include <math.h>
#include <stdint.h>

// Problem constants
#define B_     2
#define S_     2048
#define EMBED_ 2048
#define NH_    32
#define NKV_   8
#define HD_    64
#define WIN_   128
#define BS_    (B_ * S_)      // 4096
#define NQKV_  3072           // 2048 q + 512 k + 512 v

// ---------------------------------------------------------------------------
// Scratch (device globals: no allocation allowed)
// ---------------------------------------------------------------------------
__device__ float          g_qkv [BS_ * NQKV_];     // fused qkv fp32
__device__ __nv_bfloat16  g_xh  [BS_ * EMBED_];
__device__ __nv_bfloat16  g_xl  [BS_ * EMBED_];
__device__ __nv_bfloat16  g_wqkvh[NQKV_ * EMBED_];
__device__ __nv_bfloat16  g_wqkvl[NQKV_ * EMBED_];
__device__ __half         g_wo16[EMBED_ * EMBED_];   // O-proj weights, single fp16
__device__ __half         g_atth[BS_ * EMBED_];      // attention out, fp16 hi
__device__ __half         g_attl[BS_ * EMBED_];      // attention out, fp16 lo

// ---------------------------------------------------------------------------
// PTX helpers (portable sm_80+ features only: cp.async / ldmatrix / mma.sync)
// ---------------------------------------------------------------------------
__device__ __forceinline__ uint32_t smem_u32(const void* p) {
    uint32_t a;
    asm("{ .reg .u64 t; cvta.to.shared.u64 t, %1; cvt.u32.u64 %0, t; }"
        : "=r"(a) : "l"(p));
    return a;
}

#define CP_ASYNC16(sa, g) \
    asm volatile("cp.async.cg.shared.global [%0], [%1], 16;" \
                 :: "r"(sa), "l"(g) : "memory")
#define CP_COMMIT() asm volatile("cp.async.commit_group;" ::: "memory")
#define CP_WAIT(n)  asm volatile("cp.async.wait_group %0;" :: "n"(n) : "memory")

#define LDSM4(r0, r1, r2, r3, addr) \
    asm volatile("ldmatrix.sync.aligned.m8n8.x4.shared.b16 {%0,%1,%2,%3}, [%4];" \
                 : "=r"(r0), "=r"(r1), "=r"(r2), "=r"(r3) : "r"(addr))

#define MMA_BF16(c, a, b0, b1) \
    asm volatile("mma.sync.aligned.m16n8k16.row.col.f32.bf16.bf16.f32 " \
                 "{%0,%1,%2,%3}, {%4,%5,%6,%7}, {%8,%9}, {%0,%1,%2,%3};" \
                 : "+f"((c)[0]), "+f"((c)[1]), "+f"((c)[2]), "+f"((c)[3]) \
                 : "r"((a)[0]), "r"((a)[1]), "r"((a)[2]), "r"((a)[3]), \
                   "r"(b0), "r"(b1))

#define MMA_FP16(c, a, b0, b1) \
    asm volatile("mma.sync.aligned.m16n8k16.row.col.f32.f16.f16.f32 " \
                 "{%0,%1,%2,%3}, {%4,%5,%6,%7}, {%8,%9}, {%0,%1,%2,%3};" \
                 : "+f"((c)[0]), "+f"((c)[1]), "+f"((c)[2]), "+f"((c)[3]) \
                 : "r"((a)[0]), "r"((a)[1]), "r"((a)[2]), "r"((a)[3]), \
                   "r"(b0), "r"(b1))

#define GM    128
#define GN    128
#define GK    32
#define NCH   (EMBED_ / GK)         // 64
#define MAT_BYTES   (128 * 64)      // 8192 (64B rows, no pad)

// 16B chunk c (0..3) of row r lives at swizzled position c ^ ((r>>1)&3)
__device__ __forceinline__ uint32_t swz(int row, int chunk) {
    return (uint32_t)(row * 64 + ((chunk ^ ((row >> 1) & 3)) << 4));
}

// ---------------------------------------------------------------------------
// bf16-split NT GEMM (QKV): C = (Ah+Al)*(Wh+Wl)^T, 3 passes, 3-stage pipeline,
// pass-major MMA order (RAW chains spaced by 4). 2 CTAs/SM.
// ---------------------------------------------------------------------------
#define STAGE_BYTES (4 * MAT_BYTES)         // 32768: Ah, Al, Bh, Bl
#define GEMM_SMEM   (3 * STAGE_BYTES)       // 98304

__global__ void __launch_bounds__(256, 2)
gemm_bf16x3(const __nv_bfloat16* __restrict__ Ah, const __nv_bfloat16* __restrict__ Al,
            const __nv_bfloat16* __restrict__ Wh, const __nv_bfloat16* __restrict__ Wl,
            float* __restrict__ C, int N)
{
    extern __shared__ __align__(128) char sm[];
    const uint32_t smb = smem_u32(sm);

    const int tid  = threadIdx.x;
    const int warp = tid >> 5;
    const int lane = tid & 31;
    const int wm   = warp >> 1;
    const int wn   = warp & 1;

    const int m0 = blockIdx.y * GM;
    const int n0 = blockIdx.x * GN;

    const __nv_bfloat16* src[4] = {
        Ah + (size_t)m0 * EMBED_, Al + (size_t)m0 * EMBED_,
        Wh + (size_t)n0 * EMBED_, Wl + (size_t)n0 * EMBED_
    };

    const int c0row = (tid * 2) >> 2,        c0c = (tid * 2) & 3;
    const int c1row = (tid * 2 + 1) >> 2,    c1c = (tid * 2 + 1) & 3;
    const uint32_t d0 = swz(c0row, c0c);
    const uint32_t d1 = swz(c1row, c1c);

#define ISSUE_STAGE(kt, sOffv) do {                                            \
    const int _k0 = (kt) * GK;                                                 \
    const uint32_t _sb = smb + (sOffv);                                        \
    _Pragma("unroll")                                                          \
    for (int _m = 0; _m < 4; ++_m) {                                           \
        CP_ASYNC16(_sb + _m * MAT_BYTES + d0,                                  \
                   src[_m] + (size_t)c0row * EMBED_ + _k0 + c0c * 8);          \
        CP_ASYNC16(_sb + _m * MAT_BYTES + d1,                                  \
                   src[_m] + (size_t)c1row * EMBED_ + _k0 + c1c * 8);          \
    }                                                                          \
    CP_COMMIT();                                                               \
} while (0)

    float c[2][8][4];
#pragma unroll
    for (int t = 0; t < 2; t++)
#pragma unroll
        for (int nt = 0; nt < 8; nt++)
#pragma unroll
            for (int j = 0; j < 4; j++) c[t][nt][j] = 0.f;

    const int a_row  = wm * 32 + (lane & 15);
    const int a_cb   = lane >> 4;
    const int b_g8   = lane >> 3;
    const int b_row  = wn * 64 + ((b_g8 >> 1) ? 8 : 0) + (lane & 7);
    const int b_cb   = b_g8 & 1;

    ISSUE_STAGE(0, 0);
    ISSUE_STAGE(1, STAGE_BYTES);

    uint32_t sOff = 0;
    uint32_t sNext2 = 2 * STAGE_BYTES;

    for (int kt = 0; kt < NCH; ++kt) {
        if (kt + 1 < NCH) { CP_WAIT(1); }
        else              { CP_WAIT(0); }
        __syncthreads();

        if (kt + 2 < NCH) ISSUE_STAGE(kt + 2, sNext2);

        const uint32_t sb = smb + sOff;

#pragma unroll
        for (int kk = 0; kk < 2; ++kk) {
            uint32_t a[2][2][4];

#pragma unroll
            for (int hl = 0; hl < 2; ++hl)
#pragma unroll
                for (int t = 0; t < 2; ++t) {
                    int row = a_row + t * 16;
                    uint32_t ad = sb + hl * MAT_BYTES + swz(row, kk * 2 + a_cb);
                    LDSM4(a[hl][t][0], a[hl][t][1], a[hl][t][2], a[hl][t][3], ad);
                }

#pragma unroll
            for (int ntp = 0; ntp < 4; ++ntp) {
                uint32_t bh[4], bl[4];
                int row = b_row + ntp * 16;
                uint32_t bdh = sb + 2 * MAT_BYTES + swz(row, kk * 2 + b_cb);
                uint32_t bdl = bdh + MAT_BYTES;
                LDSM4(bh[0], bh[1], bh[2], bh[3], bdh);
                LDSM4(bl[0], bl[1], bl[2], bl[3], bdl);

                // pass-major: same accumulator revisited only every 4 MMAs
#pragma unroll
                for (int t = 0; t < 2; ++t)
#pragma unroll
                    for (int half = 0; half < 2; ++half)
                        MMA_BF16(c[t][ntp * 2 + half], a[0][t], bh[half*2], bh[half*2+1]);
#pragma unroll
                for (int t = 0; t < 2; ++t)
#pragma unroll
                    for (int half = 0; half < 2; ++half)
                        MMA_BF16(c[t][ntp * 2 + half], a[0][t], bl[half*2], bl[half*2+1]);
#pragma unroll
                for (int t = 0; t < 2; ++t)
#pragma unroll
                    for (int half = 0; half < 2; ++half)
                        MMA_BF16(c[t][ntp * 2 + half], a[1][t], bh[half*2], bh[half*2+1]);
            }
        }

        sOff   = (sOff   == 2 * STAGE_BYTES) ? 0 : sOff   + STAGE_BYTES;
        sNext2 = (sNext2 == 2 * STAGE_BYTES) ? 0 : sNext2 + STAGE_BYTES;
    }

#pragma unroll
    for (int t = 0; t < 2; ++t) {
        const int r0 = m0 + wm * 32 + t * 16 + (lane >> 2);
#pragma unroll
        for (int nt = 0; nt < 8; ++nt) {
            const int col = n0 + wn * 64 + nt * 8 + (lane & 3) * 2;
            *(float2*)(C + (size_t)r0 * N + col)       = make_float2(c[t][nt][0], c[t][nt][1]);
            *(float2*)(C + (size_t)(r0 + 8) * N + col) = make_float2(c[t][nt][2], c[t][nt][3]);
        }
    }
#undef ISSUE_STAGE
}

// ---------------------------------------------------------------------------
// fp16 2-pass NT GEMM (O-proj): C = (Ah+Al)*(W)^T, W single fp16.
// 2 passes: Ah*W + Al*W. 4-stage cp.async pipeline (stage = Ah,Al,W = 24KB).
// 2 CTAs/SM (192KB smem).
// ---------------------------------------------------------------------------
#define STAGE2_BYTES (3 * MAT_BYTES)        // 24576
#define GEMM2_SMEM   (4 * STAGE2_BYTES)     // 98304

__global__ void __launch_bounds__(256, 2)
gemm_fp16x2(const __half* __restrict__ Ah, const __half* __restrict__ Al,
            const __half* __restrict__ W, float* __restrict__ C, int N)
{
    extern __shared__ __align__(128) char sm[];
    const uint32_t smb = smem_u32(sm);

    const int tid  = threadIdx.x;
    const int warp = tid >> 5;
    const int lane = tid & 31;
    const int wm   = warp >> 1;
    const int wn   = warp & 1;

    const int m0 = blockIdx.y * GM;
    const int n0 = blockIdx.x * GN;

    const __half* src[3] = {
        Ah + (size_t)m0 * EMBED_, Al + (size_t)m0 * EMBED_,
        W  + (size_t)n0 * EMBED_
    };

    const int c0row = (tid * 2) >> 2,        c0c = (tid * 2) & 3;
    const int c1row = (tid * 2 + 1) >> 2,    c1c = (tid * 2 + 1) & 3;
    const uint32_t d0 = swz(c0row, c0c);
    const uint32_t d1 = swz(c1row, c1c);

#define ISSUE2(kt, sOffv) do {                                                 \
    const int _k0 = (kt) * GK;                                                 \
    const uint32_t _sb = smb + (sOffv);                                        \
    _Pragma("unroll")                                                          \
    for (int _m = 0; _m < 3; ++_m) {                                           \
        CP_ASYNC16(_sb + _m * MAT_BYTES + d0,                                  \
                   src[_m] + (size_t)c0row * EMBED_ + _k0 + c0c * 8);          \
        CP_ASYNC16(_sb + _m * MAT_BYTES + d1,                                  \
                   src[_m] + (size_t)c1row * EMBED_ + _k0 + c1c * 8);          \
    }                                                                          \
    CP_COMMIT();                                                               \
} while (0)

    float c[2][8][4];
#pragma unroll
    for (int t = 0; t < 2; t++)
#pragma unroll
        for (int nt = 0; nt < 8; nt++)
#pragma unroll
            for (int j = 0; j < 4; j++) c[t][nt][j] = 0.f;

    const int a_row  = wm * 32 + (lane & 15);
    const int a_cb   = lane >> 4;
    const int b_g8   = lane >> 3;
    const int b_row  = wn * 64 + ((b_g8 >> 1) ? 8 : 0) + (lane & 7);
    const int b_cb   = b_g8 & 1;

    ISSUE2(0, 0);
    ISSUE2(1, STAGE2_BYTES);
    ISSUE2(2, 2 * STAGE2_BYTES);

    uint32_t sOff = 0;
    uint32_t sIss = 3 * STAGE2_BYTES;

    for (int kt = 0; kt < NCH; ++kt) {
        if      (kt <= NCH - 3) { CP_WAIT(2); }
        else if (kt == NCH - 2) { CP_WAIT(1); }
        else                    { CP_WAIT(0); }
        __syncthreads();

        if (kt + 3 < NCH) ISSUE2(kt + 3, sIss);

        const uint32_t sb = smb + sOff;

#pragma unroll
        for (int kk = 0; kk < 2; ++kk) {
            uint32_t a[2][2][4];   // [hl][t]
            uint32_t b[4][4];      // [ntp]

#pragma unroll
            for (int hl = 0; hl < 2; ++hl)
#pragma unroll
                for (int t = 0; t < 2; ++t) {
                    int row = a_row + t * 16;
                    uint32_t ad = sb + hl * MAT_BYTES + swz(row, kk * 2 + a_cb);
                    LDSM4(a[hl][t][0], a[hl][t][1], a[hl][t][2], a[hl][t][3], ad);
                }
#pragma unroll
            for (int ntp = 0; ntp < 4; ++ntp) {
                int row = b_row + ntp * 16;
                uint32_t bd = sb + 2 * MAT_BYTES + swz(row, kk * 2 + b_cb);
                LDSM4(b[ntp][0], b[ntp][1], b[ntp][2], b[ntp][3], bd);
            }

            // pass-major over hl: same cc revisited every 16 MMAs
#pragma unroll
            for (int hl = 0; hl < 2; ++hl)
#pragma unroll
                for (int ntp = 0; ntp < 4; ++ntp)
#pragma unroll
                    for (int t = 0; t < 2; ++t)
#pragma unroll
                        for (int half = 0; half < 2; ++half)
                            MMA_FP16(c[t][ntp * 2 + half], a[hl][t],
                                     b[ntp][half * 2], b[ntp][half * 2 + 1]);
        }

        sOff = (sOff == 3 * STAGE2_BYTES) ? 0 : sOff + STAGE2_BYTES;
        sIss = (sIss == 3 * STAGE2_BYTES) ? 0 : sIss + STAGE2_BYTES;
    }

#pragma unroll
    for (int t = 0; t < 2; ++t) {
        const int r0 = m0 + wm * 32 + t * 16 + (lane >> 2);
#pragma unroll
        for (int nt = 0; nt < 8; ++nt) {
            const int col = n0 + wn * 64 + nt * 8 + (lane & 3) * 2;
            *(float2*)(C + (size_t)r0 * N + col)       = make_float2(c[t][nt][0], c[t][nt][1]);
            *(float2*)(C + (size_t)(r0 + 8) * N + col) = make_float2(c[t][nt][2], c[t][nt][3]);
        }
    }
#undef ISSUE2
}

// ---------------------------------------------------------------------------
// fp32 -> bf16 hi/lo split (vectorized by 4)
// ---------------------------------------------------------------------------
__global__ void split_bf16(const float* __restrict__ src,
                           __nv_bfloat16* __restrict__ h,
                           __nv_bfloat16* __restrict__ l, int n4)
{
    int i = blockIdx.x * blockDim.x + threadIdx.x;
    if (i >= n4) return;
    float4 v = ((const float4*)src)[i];
    __nv_bfloat16 h0 = __float2bfloat16(v.x);
    __nv_bfloat16 h1 = __float2bfloat16(v.y);
    __nv_bfloat16 h2 = __float2bfloat16(v.z);
    __nv_bfloat16 h3 = __float2bfloat16(v.w);
    __nv_bfloat16 l0 = __float2bfloat16(v.x - __bfloat162float(h0));
    __nv_bfloat16 l1 = __float2bfloat16(v.y - __bfloat162float(h1));
    __nv_bfloat16 l2 = __float2bfloat16(v.z - __bfloat162float(h2));
    __nv_bfloat16 l3 = __float2bfloat16(v.w - __bfloat162float(h3));
    ((__nv_bfloat162*)h)[2 * i + 0] = __nv_bfloat162(h0, h1);
    ((__nv_bfloat162*)h)[2 * i + 1] = __nv_bfloat162(h2, h3);
    ((__nv_bfloat162*)l)[2 * i + 0] = __nv_bfloat162(l0, l1);
    ((__nv_bfloat162*)l)[2 * i + 1] = __nv_bfloat162(l2, l3);
}

// fp32 -> single fp16 convert (vectorized by 4)
__global__ void convert_fp16(const float* __restrict__ src,
                             __half* __restrict__ dst, int n4)
{
    int i = blockIdx.x * blockDim.x + threadIdx.x;
    if (i >= n4) return;
    float4 v = ((const float4*)src)[i];
    ((__half2*)dst)[2 * i + 0] = __floats2half2_rn(v.x, v.y);
    ((__half2*)dst)[2 * i + 1] = __floats2half2_rn(v.z, v.w);
}

#define LOG2_10000 13.28771237954945f

// ---------------------------------------------------------------------------
// In-place RMSNorm + RoPE of the K slice of the fused qkv buffer.
// ---------------------------------------------------------------------------
__global__ void norm_k(float* __restrict__ qkv, const float* __restrict__ knw)
{
    int wrp  = (blockIdx.x * blockDim.x + threadIdx.x) >> 5;
    int lane = threadIdx.x & 31;
    if (wrp >= BS_ * NKV_) return;

    int token = wrp >> 3;
    int head  = wrp & 7;
    int s     = token & (S_ - 1);

    float* p = qkv + (size_t)token * NQKV_ + 2048 + head * HD_;
    float t1 = p[lane];
    float t2 = p[lane + 32];

    float ss = t1 * t1 + t2 * t2;
#pragma unroll
    for (int o = 16; o; o >>= 1) ss += __shfl_xor_sync(0xffffffffu, ss, o);

    float inv = rsqrtf(ss * (1.0f / 64.0f) + 1e-6f);
    t1 = t1 * inv * knw[lane];
    t2 = t2 * inv * knw[lane + 32];

    float freq = exp2f(-LOG2_10000 * (float)lane * (1.0f / 32.0f));
    float ang  = (float)s * freq;
    float sn, cs;
    sincosf(ang, &sn, &cs);

    p[lane]      = t1 * cs - t2 * sn;
    p[lane + 32] = t2 * cs + t1 * sn;
}

// ---------------------------------------------------------------------------
// Sliding-window causal attention with sink. K pre-normed; Q normed/roped in
// registers. Epilogue writes fp16 hi/lo (feeds the fp16x2 O-projection).
// ---------------------------------------------------------------------------
#define TQ      64
#define KMAX    192
#define KSTRIDE 68

__global__ void __launch_bounds__(256, 2)
attn_kernel(const float* __restrict__ qkv, const int* __restrict__ mask,
            const float* __restrict__ sinks, const float* __restrict__ qnw,
            __half* __restrict__ outh, __half* __restrict__ outl)
{
    extern __shared__ float smf[];
    float* sK    = smf;
    float* sV    = smf + KMAX * KSTRIDE;
    float* sBias = smf + 2 * KMAX * KSTRIDE;

    const int b  = blockIdx.z;
    const int h  = blockIdx.y;
    const int q0 = blockIdx.x * TQ;
    const int kv = h >> 2;

    int kbase = q0 - (WIN_ - 1); if (kbase < 0) kbase = 0;
    const int nk = q0 + TQ - 1 - kbase + 1;

    for (int idx = threadIdx.x; idx < nk * 16; idx += blockDim.x) {
        int key = idx >> 4;
        int c4  = (idx & 15) << 2;
        size_t base = (size_t)(b * S_ + kbase + key) * NQKV_ + kv * HD_ + c4;
        float4 kr = *(const float4*)(qkv + base + 2048);
        float4 vr = *(const float4*)(qkv + base + 2560);
        *(float4*)(sK + key * KSTRIDE + c4) = kr;
        *(float4*)(sV + key * KSTRIDE + c4) = vr;
    }
    for (int idx = threadIdx.x; idx < nk; idx += blockDim.x)
        sBias[idx] = (mask[b * S_ + kbase + idx] > 0) ? 0.0f : -1e30f;
    __syncthreads();

    const int qloc = threadIdx.x >> 2;
    const int g    = threadIdx.x & 3;
    const int qg   = q0 + qloc;
    const int lane = threadIdx.x & 31;
    const unsigned gmask = 0xFu << (lane & ~3);

    float qr[16];
    const float* qp = qkv + (size_t)(b * S_ + qg) * NQKV_ + h * HD_;
#pragma unroll
    for (int i = 0; i < 8; i += 4) {
        float4 t = *(const float4*)(qp + g * 8 + i);
        qr[i] = t.x; qr[i+1] = t.y; qr[i+2] = t.z; qr[i+3] = t.w;
        float4 u = *(const float4*)(qp + 32 + g * 8 + i);
        qr[8+i] = u.x; qr[9+i] = u.y; qr[10+i] = u.z; qr[11+i] = u.w;
    }

    {
        float ss = 0.f;
#pragma unroll
        for (int i = 0; i < 16; i++) ss += qr[i] * qr[i];
        ss += __shfl_xor_sync(gmask, ss, 1);
        ss += __shfl_xor_sync(gmask, ss, 2);
        float inv = rsqrtf(ss * (1.0f / 64.0f) + 1e-6f);
#pragma unroll
        for (int i = 0; i < 8; i++) {
            qr[i]     *= inv * qnw[g * 8 + i];
            qr[i + 8] *= inv * qnw[32 + g * 8 + i];
        }
#pragma unroll
        for (int i = 0; i < 8; i++) {
            int d = g * 8 + i;
            float freq = exp2f(-LOG2_10000 * (float)d * (1.0f / 32.0f));
            float ang  = (float)qg * freq;
            float sn, cs;
            sincosf(ang, &sn, &cs);
            float t1 = qr[i], t2 = qr[i + 8];
            qr[i]     = t1 * cs - t2 * sn;
            qr[i + 8] = t2 * cs + t1 * sn;
        }
    }

    float m = sinks[h];
    float l = 1.0f;
    float acc[16];
#pragma unroll
    for (int i = 0; i < 16; i++) acc[i] = 0.f;

    int ks = qg - (WIN_ - 1); if (ks < 0) ks = 0;
    const float scale = 0.125f;

    for (int kk = ks; kk <= qg; kk++) {
        const int kl = kk - kbase;
        const float* kp = sK + kl * KSTRIDE;
        float s = 0.f;
#pragma unroll
        for (int i = 0; i < 8; i += 4) {
            float4 k4 = *(const float4*)(kp + g * 8 + i);
            s = fmaf(qr[i],   k4.x, s);
            s = fmaf(qr[i+1], k4.y, s);
            s = fmaf(qr[i+2], k4.z, s);
            s = fmaf(qr[i+3], k4.w, s);
            float4 k5 = *(const float4*)(kp + 32 + g * 8 + i);
            s = fmaf(qr[8+i],  k5.x, s);
            s = fmaf(qr[9+i],  k5.y, s);
            s = fmaf(qr[10+i], k5.z, s);
            s = fmaf(qr[11+i], k5.w, s);
        }
        s += __shfl_xor_sync(gmask, s, 1);
        s += __shfl_xor_sync(gmask, s, 2);
        s = s * scale + sBias[kl];

        float mnew = fmaxf(m, s);
        float corr = __expf(m - mnew);
        float p    = __expf(s - mnew);
        l = l * corr + p;
        m = mnew;

        const float* vp = sV + kl * KSTRIDE;
#pragma unroll
        for (int i = 0; i < 8; i += 4) {
            float4 v4 = *(const float4*)(vp + g * 8 + i);
            acc[i]   = acc[i]   * corr + p * v4.x;
            acc[i+1] = acc[i+1] * corr + p * v4.y;
            acc[i+2] = acc[i+2] * corr + p * v4.z;
            acc[i+3] = acc[i+3] * corr + p * v4.w;
            float4 v5 = *(const float4*)(vp + 32 + g * 8 + i);
            acc[8+i]  = acc[8+i]  * corr + p * v5.x;
            acc[9+i]  = acc[9+i]  * corr + p * v5.y;
            acc[10+i] = acc[10+i] * corr + p * v5.z;
            acc[11+i] = acc[11+i] * corr + p * v5.w;
        }
    }

    const float invl = 1.0f / l;
    size_t ob = (size_t)(b * S_ + qg) * EMBED_ + h * HD_ + g * 8;
#pragma unroll
    for (int seg = 0; seg < 2; seg++) {
        size_t o = ob + seg * 32;
        const float* a = acc + seg * 8;
#pragma unroll
        for (int i = 0; i < 8; i += 2) {
            float v0 = a[i] * invl, v1 = a[i+1] * invl;
            __half h0 = __float2half_rn(v0);
            __half h1 = __float2half_rn(v1);
            __half l0 = __float2half_rn(v0 - __half2float(h0));
            __half l1 = __float2half_rn(v1 - __half2float(h1));
            *(__half2*)(outh + o + i) = __halves2half2(h0, h1);
            *(__half2*)(outl + o + i) = __halves2half2(l0, l1);
        }
    }
}

// ---------------------------------------------------------------------------
// Launch
// ---------------------------------------------------------------------------
extern "C" void kernel_launch(void* const* d_in, const int* in_sizes, int n_in,
                              void* d_out, int out_size)
{
    const float* x      = (const float*)d_in[0];
    const int*   amask  = (const int*)d_in[1];
    const float* wq     = (const float*)d_in[2];
    const float* wk     = (const float*)d_in[3];
    const float* wv     = (const float*)d_in[4];
    const float* wo     = (const float*)d_in[5];
    const float* qnw    = (const float*)d_in[6];
    const float* knw    = (const float*)d_in[7];
    const float* sinks  = (const float*)d_in[8];
    float*       out    = (float*)d_out;

    float *qkvb;
    __nv_bfloat16 *xh, *xl, *wqkvh, *wqkvl;
    __half *wo16, *atth, *attl;
    cudaGetSymbolAddress((void**)&qkvb,  g_qkv);
    cudaGetSymbolAddress((void**)&xh,    g_xh);
    cudaGetSymbolAddress((void**)&xl,    g_xl);
    cudaGetSymbolAddress((void**)&wqkvh, g_wqkvh);
    cudaGetSymbolAddress((void**)&wqkvl, g_wqkvl);
    cudaGetSymbolAddress((void**)&wo16,  g_wo16);
    cudaGetSymbolAddress((void**)&atth,  g_atth);
    cudaGetSymbolAddress((void**)&attl,  g_attl);

    cudaFuncSetAttribute(gemm_bf16x3,
                         cudaFuncAttributeMaxDynamicSharedMemorySize, GEMM_SMEM);
    cudaFuncSetAttribute(gemm_fp16x2,
                         cudaFuncAttributeMaxDynamicSharedMemorySize, GEMM2_SMEM);

    // splits for the QKV GEMM
    split_bf16<<<(BS_ * EMBED_ / 4 + 255) / 256, 256>>>(x, xh, xl, BS_ * EMBED_ / 4);
    split_bf16<<<(2048 * EMBED_ / 4 + 255) / 256, 256>>>(wq, wqkvh, wqkvl, 2048 * EMBED_ / 4);
    split_bf16<<<(512 * EMBED_ / 4 + 255) / 256, 256>>>(
        wk, wqkvh + (size_t)2048 * EMBED_, wqkvl + (size_t)2048 * EMBED_, 512 * EMBED_ / 4);
    split_bf16<<<(512 * EMBED_ / 4 + 255) / 256, 256>>>(
        wv, wqkvh + (size_t)2560 * EMBED_, wqkvl + (size_t)2560 * EMBED_, 512 * EMBED_ / 4);

    // fused QKV projection (bf16x3)
    gemm_bf16x3<<<dim3(NQKV_ / GN, BS_ / GM), 256, GEMM_SMEM>>>(
        xh, xl, wqkvh, wqkvl, qkvb, NQKV_);

    // K rmsnorm+rope, once (in place)
    norm_k<<<(BS_ * NKV_ * 32 + 255) / 256, 256>>>(qkvb, knw);

    // attention: fused q-norm/rope + sliding-window softmax + fp16 split out
    {
        size_t smem = (size_t)(2 * KMAX * KSTRIDE + KMAX) * sizeof(float);
        cudaFuncSetAttribute(attn_kernel,
                             cudaFuncAttributeMaxDynamicSharedMemorySize, (int)smem);
        dim3 grid(S_ / TQ, NH_, B_);
        attn_kernel<<<grid, 256, smem>>>(qkvb, amask, sinks, qnw, atth, attl);
    }

    // wo -> fp16, then O projection (fp16 2-pass)
    convert_fp16<<<(EMBED_ * EMBED_ / 4 + 255) / 256, 256>>>(wo, wo16, EMBED_ * EMBED_ / 4);
    gemm_fp16x2<<<dim3(EMBED_ / GN, BS_ / GM), 256, GEMM2_SMEM>>>(
        atth, attl, wo16, out, EMBED_);
}

// round 15
// speedup vs baseline: 1.5604x; 1.5604x over previous
#include <cuda_runtime.h>
#include <cuda_bf16.h>
#include <cuda_fp16.h>
#include <math.h>
#include <stdint.h>

// Problem constants
#define B_     2
#define S_     2048
#define EMBED_ 2048
#define NH_    32
#define NKV_   8
#define HD_    64
#define WIN_   128
#define BS_    (B_ * S_)      // 4096
#define NQKV_  3072           // 2048 q + 512 k + 512 v

// ---------------------------------------------------------------------------
// Scratch (device globals: no allocation allowed)
// ---------------------------------------------------------------------------
__device__ float          g_qkv [BS_ * NQKV_];     // fused qkv fp32
__device__ __nv_bfloat16  g_xh  [BS_ * EMBED_];
__device__ __nv_bfloat16  g_xl  [BS_ * EMBED_];
__device__ __nv_bfloat16  g_wqkvh[NQKV_ * EMBED_];
__device__ __nv_bfloat16  g_wqkvl[NQKV_ * EMBED_];
__device__ __half         g_wo16[EMBED_ * EMBED_];   // O-proj weights, single fp16
__device__ __half         g_atth[BS_ * EMBED_];      // attention out, fp16 hi
__device__ __half         g_attl[BS_ * EMBED_];      // attention out, fp16 lo

// ---------------------------------------------------------------------------
// PTX helpers (portable sm_80+ features only: cp.async / ldmatrix / mma.sync)
// ---------------------------------------------------------------------------
__device__ __forceinline__ uint32_t smem_u32(const void* p) {
    uint32_t a;
    asm("{ .reg .u64 t; cvta.to.shared.u64 t, %1; cvt.u32.u64 %0, t; }"
        : "=r"(a) : "l"(p));
    return a;
}

#define CP_ASYNC16(sa, g) \
    asm volatile("cp.async.cg.shared.global [%0], [%1], 16;" \
                 :: "r"(sa), "l"(g) : "memory")
#define CP_COMMIT() asm volatile("cp.async.commit_group;" ::: "memory")
#define CP_WAIT(n)  asm volatile("cp.async.wait_group %0;" :: "n"(n) : "memory")

#define LDSM4(r0, r1, r2, r3, addr) \
    asm volatile("ldmatrix.sync.aligned.m8n8.x4.shared.b16 {%0,%1,%2,%3}, [%4];" \
                 : "=r"(r0), "=r"(r1), "=r"(r2), "=r"(r3) : "r"(addr))

#define MMA_BF16(c, a, b0, b1) \
    asm volatile("mma.sync.aligned.m16n8k16.row.col.f32.bf16.bf16.f32 " \
                 "{%0,%1,%2,%3}, {%4,%5,%6,%7}, {%8,%9}, {%0,%1,%2,%3};" \
                 : "+f"((c)[0]), "+f"((c)[1]), "+f"((c)[2]), "+f"((c)[3]) \
                 : "r"((a)[0]), "r"((a)[1]), "r"((a)[2]), "r"((a)[3]), \
                   "r"(b0), "r"(b1))

#define MMA_FP16(c, a, b0, b1) \
    asm volatile("mma.sync.aligned.m16n8k16.row.col.f32.f16.f16.f32 " \
                 "{%0,%1,%2,%3}, {%4,%5,%6,%7}, {%8,%9}, {%0,%1,%2,%3};" \
                 : "+f"((c)[0]), "+f"((c)[1]), "+f"((c)[2]), "+f"((c)[3]) \
                 : "r"((a)[0]), "r"((a)[1]), "r"((a)[2]), "r"((a)[3]), \
                   "r"(b0), "r"(b1))

#define GM    128
#define GN    128
#define GK    32
#define NCH   (EMBED_ / GK)         // 64
#define MAT_BYTES   (128 * 64)      // 8192 (64B rows, no pad)

// 16B chunk c (0..3) of row r lives at swizzled position c ^ ((r>>1)&3)
__device__ __forceinline__ uint32_t swz(int row, int chunk) {
    return (uint32_t)(row * 64 + ((chunk ^ ((row >> 1) & 3)) << 4));
}

// ---------------------------------------------------------------------------
// bf16-split NT GEMM (QKV): C = (Ah+Al)*(Wh+Wl)^T, 3 passes, 3-stage pipeline
// EXACT R12 winner (interleaved MMA order). 2 CTAs/SM.
// ---------------------------------------------------------------------------
#define STAGE_BYTES (4 * MAT_BYTES)         // 32768: Ah, Al, Bh, Bl
#define GEMM_SMEM   (3 * STAGE_BYTES)       // 98304

__global__ void __launch_bounds__(256, 2)
gemm_bf16x3(const __nv_bfloat16* __restrict__ Ah, const __nv_bfloat16* __restrict__ Al,
            const __nv_bfloat16* __restrict__ Wh, const __nv_bfloat16* __restrict__ Wl,
            float* __restrict__ C, int N)
{
    extern __shared__ __align__(128) char sm[];
    const uint32_t smb = smem_u32(sm);

    const int tid  = threadIdx.x;
    const int warp = tid >> 5;
    const int lane = tid & 31;
    const int wm   = warp >> 1;
    const int wn   = warp & 1;

    const int m0 = blockIdx.y * GM;
    const int n0 = blockIdx.x * GN;

    const __nv_bfloat16* src[4] = {
        Ah + (size_t)m0 * EMBED_, Al + (size_t)m0 * EMBED_,
        Wh + (size_t)n0 * EMBED_, Wl + (size_t)n0 * EMBED_
    };

    const int c0row = (tid * 2) >> 2,        c0c = (tid * 2) & 3;
    const int c1row = (tid * 2 + 1) >> 2,    c1c = (tid * 2 + 1) & 3;
    const uint32_t d0 = swz(c0row, c0c);
    const uint32_t d1 = swz(c1row, c1c);

#define ISSUE_STAGE(kt, sOffv) do {                                            \
    const int _k0 = (kt) * GK;                                                 \
    const uint32_t _sb = smb + (sOffv);                                        \
    _Pragma("unroll")                                                          \
    for (int _m = 0; _m < 4; ++_m) {                                           \
        CP_ASYNC16(_sb + _m * MAT_BYTES + d0,                                  \
                   src[_m] + (size_t)c0row * EMBED_ + _k0 + c0c * 8);          \
        CP_ASYNC16(_sb + _m * MAT_BYTES + d1,                                  \
                   src[_m] + (size_t)c1row * EMBED_ + _k0 + c1c * 8);          \
    }                                                                          \
    CP_COMMIT();                                                               \
} while (0)

    float c[2][8][4];
#pragma unroll
    for (int t = 0; t < 2; t++)
#pragma unroll
        for (int nt = 0; nt < 8; nt++)
#pragma unroll
            for (int j = 0; j < 4; j++) c[t][nt][j] = 0.f;

    const int a_row  = wm * 32 + (lane & 15);
    const int a_cb   = lane >> 4;
    const int b_g8   = lane >> 3;
    const int b_row  = wn * 64 + ((b_g8 >> 1) ? 8 : 0) + (lane & 7);
    const int b_cb   = b_g8 & 1;

    ISSUE_STAGE(0, 0);
    ISSUE_STAGE(1, STAGE_BYTES);

    uint32_t sOff = 0;
    uint32_t sNext2 = 2 * STAGE_BYTES;

    for (int kt = 0; kt < NCH; ++kt) {
        if (kt + 1 < NCH) { CP_WAIT(1); }
        else              { CP_WAIT(0); }
        __syncthreads();

        if (kt + 2 < NCH) ISSUE_STAGE(kt + 2, sNext2);

        const uint32_t sb = smb + sOff;

#pragma unroll
        for (int kk = 0; kk < 2; ++kk) {
            uint32_t a[2][2][4];

#pragma unroll
            for (int hl = 0; hl < 2; ++hl)
#pragma unroll
                for (int t = 0; t < 2; ++t) {
                    int row = a_row + t * 16;
                    uint32_t ad = sb + hl * MAT_BYTES + swz(row, kk * 2 + a_cb);
                    LDSM4(a[hl][t][0], a[hl][t][1], a[hl][t][2], a[hl][t][3], ad);
                }

#pragma unroll
            for (int ntp = 0; ntp < 4; ++ntp) {
                uint32_t bh[4], bl[4];
                int row = b_row + ntp * 16;
                uint32_t bdh = sb + 2 * MAT_BYTES + swz(row, kk * 2 + b_cb);
                uint32_t bdl = bdh + MAT_BYTES;
                LDSM4(bh[0], bh[1], bh[2], bh[3], bdh);
                LDSM4(bl[0], bl[1], bl[2], bl[3], bdl);

#pragma unroll
                for (int t = 0; t < 2; ++t)
#pragma unroll
                    for (int half = 0; half < 2; ++half) {
                        float* cc = c[t][ntp * 2 + half];
                        MMA_BF16(cc, a[0][t], bh[half * 2], bh[half * 2 + 1]); // Ah*Bh
                        MMA_BF16(cc, a[0][t], bl[half * 2], bl[half * 2 + 1]); // Ah*Bl
                        MMA_BF16(cc, a[1][t], bh[half * 2], bh[half * 2 + 1]); // Al*Bh
                    }
            }
        }

        sOff   = (sOff   == 2 * STAGE_BYTES) ? 0 : sOff   + STAGE_BYTES;
        sNext2 = (sNext2 == 2 * STAGE_BYTES) ? 0 : sNext2 + STAGE_BYTES;
    }

#pragma unroll
    for (int t = 0; t < 2; ++t) {
        const int r0 = m0 + wm * 32 + t * 16 + (lane >> 2);
#pragma unroll
        for (int nt = 0; nt < 8; ++nt) {
            const int col = n0 + wn * 64 + nt * 8 + (lane & 3) * 2;
            *(float2*)(C + (size_t)r0 * N + col)       = make_float2(c[t][nt][0], c[t][nt][1]);
            *(float2*)(C + (size_t)(r0 + 8) * N + col) = make_float2(c[t][nt][2], c[t][nt][3]);
        }
    }
#undef ISSUE_STAGE
}

// ---------------------------------------------------------------------------
// fp16 2-pass NT GEMM (O-proj): C = (Ah+Al)*W^T, W single fp16.
// STRUCTURAL CLONE of the proven bf16x3 kernel: 3-stage pipeline, per-ntp
// single B LDSM (4 B-regs live), interleaved 2 MMAs per accumulator.
// Stage = Ah, Al, W = 24KB; 3 stages = 72KB; 2 CTAs/SM.
// ---------------------------------------------------------------------------
#define STAGE2_BYTES (3 * MAT_BYTES)        // 24576
#define GEMM2_SMEM   (3 * STAGE2_BYTES)     // 73728

__global__ void __launch_bounds__(256, 2)
gemm_fp16x2(const __half* __restrict__ Ah, const __half* __restrict__ Al,
            const __half* __restrict__ W, float* __restrict__ C, int N)
{
    extern __shared__ __align__(128) char sm[];
    const uint32_t smb = smem_u32(sm);

    const int tid  = threadIdx.x;
    const int warp = tid >> 5;
    const int lane = tid & 31;
    const int wm   = warp >> 1;
    const int wn   = warp & 1;

    const int m0 = blockIdx.y * GM;
    const int n0 = blockIdx.x * GN;

    const __half* src[3] = {
        Ah + (size_t)m0 * EMBED_, Al + (size_t)m0 * EMBED_,
        W  + (size_t)n0 * EMBED_
    };

    const int c0row = (tid * 2) >> 2,        c0c = (tid * 2) & 3;
    const int c1row = (tid * 2 + 1) >> 2,    c1c = (tid * 2 + 1) & 3;
    const uint32_t d0 = swz(c0row, c0c);
    const uint32_t d1 = swz(c1row, c1c);

#define ISSUE2(kt, sOffv) do {                                                 \
    const int _k0 = (kt) * GK;                                                 \
    const uint32_t _sb = smb + (sOffv);                                        \
    _Pragma("unroll")                                                          \
    for (int _m = 0; _m < 3; ++_m) {                                           \
        CP_ASYNC16(_sb + _m * MAT_BYTES + d0,                                  \
                   src[_m] + (size_t)c0row * EMBED_ + _k0 + c0c * 8);          \
        CP_ASYNC16(_sb + _m * MAT_BYTES + d1,                                  \
                   src[_m] + (size_t)c1row * EMBED_ + _k0 + c1c * 8);          \
    }                                                                          \
    CP_COMMIT();                                                               \
} while (0)

    float c[2][8][4];
#pragma unroll
    for (int t = 0; t < 2; t++)
#pragma unroll
        for (int nt = 0; nt < 8; nt++)
#pragma unroll
            for (int j = 0; j < 4; j++) c[t][nt][j] = 0.f;

    const int a_row  = wm * 32 + (lane & 15);
    const int a_cb   = lane >> 4;
    const int b_g8   = lane >> 3;
    const int b_row  = wn * 64 + ((b_g8 >> 1) ? 8 : 0) + (lane & 7);
    const int b_cb   = b_g8 & 1;

    ISSUE2(0, 0);
    ISSUE2(1, STAGE2_BYTES);

    uint32_t sOff = 0;
    uint32_t sNext2 = 2 * STAGE2_BYTES;

    for (int kt = 0; kt < NCH; ++kt) {
        if (kt + 1 < NCH) { CP_WAIT(1); }
        else              { CP_WAIT(0); }
        __syncthreads();

        if (kt + 2 < NCH) ISSUE2(kt + 2, sNext2);

        const uint32_t sb = smb + sOff;

#pragma unroll
        for (int kk = 0; kk < 2; ++kk) {
            uint32_t a[2][2][4];

#pragma unroll
            for (int hl = 0; hl < 2; ++hl)
#pragma unroll
                for (int t = 0; t < 2; ++t) {
                    int row = a_row + t * 16;
                    uint32_t ad = sb + hl * MAT_BYTES + swz(row, kk * 2 + a_cb);
                    LDSM4(a[hl][t][0], a[hl][t][1], a[hl][t][2], a[hl][t][3], ad);
                }

#pragma unroll
            for (int ntp = 0; ntp < 4; ++ntp) {
                uint32_t b[4];
                int row = b_row + ntp * 16;
                uint32_t bd = sb + 2 * MAT_BYTES + swz(row, kk * 2 + b_cb);
                LDSM4(b[0], b[1], b[2], b[3], bd);

#pragma unroll
                for (int t = 0; t < 2; ++t)
#pragma unroll
                    for (int half = 0; half < 2; ++half) {
                        float* cc = c[t][ntp * 2 + half];
                        MMA_FP16(cc, a[0][t], b[half * 2], b[half * 2 + 1]); // Ah*W
                        MMA_FP16(cc, a[1][t], b[half * 2], b[half * 2 + 1]); // Al*W
                    }
            }
        }

        sOff   = (sOff   == 2 * STAGE2_BYTES) ? 0 : sOff   + STAGE2_BYTES;
        sNext2 = (sNext2 == 2 * STAGE2_BYTES) ? 0 : sNext2 + STAGE2_BYTES;
    }

#pragma unroll
    for (int t = 0; t < 2; ++t) {
        const int r0 = m0 + wm * 32 + t * 16 + (lane >> 2);
#pragma unroll
        for (int nt = 0; nt < 8; ++nt) {
            const int col = n0 + wn * 64 + nt * 8 + (lane & 3) * 2;
            *(float2*)(C + (size_t)r0 * N + col)       = make_float2(c[t][nt][0], c[t][nt][1]);
            *(float2*)(C + (size_t)(r0 + 8) * N + col) = make_float2(c[t][nt][2], c[t][nt][3]);
        }
    }
#undef ISSUE2
}

// ---------------------------------------------------------------------------
// fp32 -> bf16 hi/lo split (vectorized by 4)
// ---------------------------------------------------------------------------
__global__ void split_bf16(const float* __restrict__ src,
                           __nv_bfloat16* __restrict__ h,
                           __nv_bfloat16* __restrict__ l, int n4)
{
    int i = blockIdx.x * blockDim.x + threadIdx.x;
    if (i >= n4) return;
    float4 v = ((const float4*)src)[i];
    __nv_bfloat16 h0 = __float2bfloat16(v.x);
    __nv_bfloat16 h1 = __float2bfloat16(v.y);
    __nv_bfloat16 h2 = __float2bfloat16(v.z);
    __nv_bfloat16 h3 = __float2bfloat16(v.w);
    __nv_bfloat16 l0 = __float2bfloat16(v.x - __bfloat162float(h0));
    __nv_bfloat16 l1 = __float2bfloat16(v.y - __bfloat162float(h1));
    __nv_bfloat16 l2 = __float2bfloat16(v.z - __bfloat162float(h2));
    __nv_bfloat16 l3 = __float2bfloat16(v.w - __bfloat162float(h3));
    ((__nv_bfloat162*)h)[2 * i + 0] = __nv_bfloat162(h0, h1);
    ((__nv_bfloat162*)h)[2 * i + 1] = __nv_bfloat162(h2, h3);
    ((__nv_bfloat162*)l)[2 * i + 0] = __nv_bfloat162(l0, l1);
    ((__nv_bfloat162*)l)[2 * i + 1] = __nv_bfloat162(l2, l3);
}

// fp32 -> single fp16 convert (vectorized by 4)
__global__ void convert_fp16(const float* __restrict__ src,
                             __half* __restrict__ dst, int n4)
{
    int i = blockIdx.x * blockDim.x + threadIdx.x;
    if (i >= n4) return;
    float4 v = ((const float4*)src)[i];
    ((__half2*)dst)[2 * i + 0] = __floats2half2_rn(v.x, v.y);
    ((__half2*)dst)[2 * i + 1] = __floats2half2_rn(v.z, v.w);
}

#define LOG2_10000 13.28771237954945f

// ---------------------------------------------------------------------------
// In-place RMSNorm + RoPE of the K slice of the fused qkv buffer.
// ---------------------------------------------------------------------------
__global__ void norm_k(float* __restrict__ qkv, const float* __restrict__ knw)
{
    int wrp  = (blockIdx.x * blockDim.x + threadIdx.x) >> 5;
    int lane = threadIdx.x & 31;
    if (wrp >= BS_ * NKV_) return;

    int token = wrp >> 3;
    int head  = wrp & 7;
    int s     = token & (S_ - 1);

    float* p = qkv + (size_t)token * NQKV_ + 2048 + head * HD_;
    float t1 = p[lane];
    float t2 = p[lane + 32];

    float ss = t1 * t1 + t2 * t2;
#pragma unroll
    for (int o = 16; o; o >>= 1) ss += __shfl_xor_sync(0xffffffffu, ss, o);

    float inv = rsqrtf(ss * (1.0f / 64.0f) + 1e-6f);
    t1 = t1 * inv * knw[lane];
    t2 = t2 * inv * knw[lane + 32];

    float freq = exp2f(-LOG2_10000 * (float)lane * (1.0f / 32.0f));
    float ang  = (float)s * freq;
    float sn, cs;
    sincosf(ang, &sn, &cs);

    p[lane]      = t1 * cs - t2 * sn;
    p[lane + 32] = t2 * cs + t1 * sn;
}

// ---------------------------------------------------------------------------
// Sliding-window causal attention with sink. K pre-normed; Q normed/roped in
// registers. Epilogue writes fp16 hi/lo (feeds the fp16x2 O-projection).
// ---------------------------------------------------------------------------
#define TQ      64
#define KMAX    192
#define KSTRIDE 68

__global__ void __launch_bounds__(256, 2)
attn_kernel(const float* __restrict__ qkv, const int* __restrict__ mask,
            const float* __restrict__ sinks, const float* __restrict__ qnw,
            __half* __restrict__ outh, __half* __restrict__ outl)
{
    extern __shared__ float smf[];
    float* sK    = smf;
    float* sV    = smf + KMAX * KSTRIDE;
    float* sBias = smf + 2 * KMAX * KSTRIDE;

    const int b  = blockIdx.z;
    const int h  = blockIdx.y;
    const int q0 = blockIdx.x * TQ;
    const int kv = h >> 2;

    int kbase = q0 - (WIN_ - 1); if (kbase < 0) kbase = 0;
    const int nk = q0 + TQ - 1 - kbase + 1;

    for (int idx = threadIdx.x; idx < nk * 16; idx += blockDim.x) {
        int key = idx >> 4;
        int c4  = (idx & 15) << 2;
        size_t base = (size_t)(b * S_ + kbase + key) * NQKV_ + kv * HD_ + c4;
        float4 kr = *(const float4*)(qkv + base + 2048);
        float4 vr = *(const float4*)(qkv + base + 2560);
        *(float4*)(sK + key * KSTRIDE + c4) = kr;
        *(float4*)(sV + key * KSTRIDE + c4) = vr;
    }
    for (int idx = threadIdx.x; idx < nk; idx += blockDim.x)
        sBias[idx] = (mask[b * S_ + kbase + idx] > 0) ? 0.0f : -1e30f;
    __syncthreads();

    const int qloc = threadIdx.x >> 2;
    const int g    = threadIdx.x & 3;
    const int qg   = q0 + qloc;
    const int lane = threadIdx.x & 31;
    const unsigned gmask = 0xFu << (lane & ~3);

    float qr[16];
    const float* qp = qkv + (size_t)(b * S_ + qg) * NQKV_ + h * HD_;
#pragma unroll
    for (int i = 0; i < 8; i += 4) {
        float4 t = *(const float4*)(qp + g * 8 + i);
        qr[i] = t.x; qr[i+1] = t.y; qr[i+2] = t.z; qr[i+3] = t.w;
        float4 u = *(const float4*)(qp + 32 + g * 8 + i);
        qr[8+i] = u.x; qr[9+i] = u.y; qr[10+i] = u.z; qr[11+i] = u.w;
    }

    {
        float ss = 0.f;
#pragma unroll
        for (int i = 0; i < 16; i++) ss += qr[i] * qr[i];
        ss += __shfl_xor_sync(gmask, ss, 1);
        ss += __shfl_xor_sync(gmask, ss, 2);
        float inv = rsqrtf(ss * (1.0f / 64.0f) + 1e-6f);
#pragma unroll
        for (int i = 0; i < 8; i++) {
            qr[i]     *= inv * qnw[g * 8 + i];
            qr[i + 8] *= inv * qnw[32 + g * 8 + i];
        }
#pragma unroll
        for (int i = 0; i < 8; i++) {
            int d = g * 8 + i;
            float freq = exp2f(-LOG2_10000 * (float)d * (1.0f / 32.0f));
            float ang  = (float)qg * freq;
            float sn, cs;
            sincosf(ang, &sn, &cs);
            float t1 = qr[i], t2 = qr[i + 8];
            qr[i]     = t1 * cs - t2 * sn;
            qr[i + 8] = t2 * cs + t1 * sn;
        }
    }

    float m = sinks[h];
    float l = 1.0f;
    float acc[16];
#pragma unroll
    for (int i = 0; i < 16; i++) acc[i] = 0.f;

    int ks = qg - (WIN_ - 1); if (ks < 0) ks = 0;
    const float scale = 0.125f;

    for (int kk = ks; kk <= qg; kk++) {
        const int kl = kk - kbase;
        const float* kp = sK + kl * KSTRIDE;
        float s = 0.f;
#pragma unroll
        for (int i = 0; i < 8; i += 4) {
            float4 k4 = *(const float4*)(kp + g * 8 + i);
            s = fmaf(qr[i],   k4.x, s);
            s = fmaf(qr[i+1], k4.y, s);
            s = fmaf(qr[i+2], k4.z, s);
            s = fmaf(qr[i+3], k4.w, s);
            float4 k5 = *(const float4*)(kp + 32 + g * 8 + i);
            s = fmaf(qr[8+i],  k5.x, s);
            s = fmaf(qr[9+i],  k5.y, s);
            s = fmaf(qr[10+i], k5.z, s);
            s = fmaf(qr[11+i], k5.w, s);
        }
        s += __shfl_xor_sync(gmask, s, 1);
        s += __shfl_xor_sync(gmask, s, 2);
        s = s * scale + sBias[kl];

        float mnew = fmaxf(m, s);
        float corr = __expf(m - mnew);
        float p    = __expf(s - mnew);
        l = l * corr + p;
        m = mnew;

        const float* vp = sV + kl * KSTRIDE;
#pragma unroll
        for (int i = 0; i < 8; i += 4) {
            float4 v4 = *(const float4*)(vp + g * 8 + i);
            acc[i]   = acc[i]   * corr + p * v4.x;
            acc[i+1] = acc[i+1] * corr + p * v4.y;
            acc[i+2] = acc[i+2] * corr + p * v4.z;
            acc[i+3] = acc[i+3] * corr + p * v4.w;
            float4 v5 = *(const float4*)(vp + 32 + g * 8 + i);
            acc[8+i]  = acc[8+i]  * corr + p * v5.x;
            acc[9+i]  = acc[9+i]  * corr + p * v5.y;
            acc[10+i] = acc[10+i] * corr + p * v5.z;
            acc[11+i] = acc[11+i] * corr + p * v5.w;
        }
    }

    const float invl = 1.0f / l;
    size_t ob = (size_t)(b * S_ + qg) * EMBED_ + h * HD_ + g * 8;
#pragma unroll
    for (int seg = 0; seg < 2; seg++) {
        size_t o = ob + seg * 32;
        const float* a = acc + seg * 8;
#pragma unroll
        for (int i = 0; i < 8; i += 2) {
            float v0 = a[i] * invl, v1 = a[i+1] * invl;
            __half h0 = __float2half_rn(v0);
            __half h1 = __float2half_rn(v1);
            __half l0 = __float2half_rn(v0 - __half2float(h0));
            __half l1 = __float2half_rn(v1 - __half2float(h1));
            *(__half2*)(outh + o + i) = __halves2half2(h0, h1);
            *(__half2*)(outl + o + i) = __halves2half2(l0, l1);
        }
    }
}

// ---------------------------------------------------------------------------
// Launch
// ---------------------------------------------------------------------------
extern "C" void kernel_launch(void* const* d_in, const int* in_sizes, int n_in,
                              void* d_out, int out_size)
{
    const float* x      = (const float*)d_in[0];
    const int*   amask  = (const int*)d_in[1];
    const float* wq     = (const float*)d_in[2];
    const float* wk     = (const float*)d_in[3];
    const float* wv     = (const float*)d_in[4];
    const float* wo     = (const float*)d_in[5];
    const float* qnw    = (const float*)d_in[6];
    const float* knw    = (const float*)d_in[7];
    const float* sinks  = (const float*)d_in[8];
    float*       out    = (float*)d_out;

    float *qkvb;
    __nv_bfloat16 *xh, *xl, *wqkvh, *wqkvl;
    __half *wo16, *atth, *attl;
    cudaGetSymbolAddress((void**)&qkvb,  g_qkv);
    cudaGetSymbolAddress((void**)&xh,    g_xh);
    cudaGetSymbolAddress((void**)&xl,    g_xl);
    cudaGetSymbolAddress((void**)&wqkvh, g_wqkvh);
    cudaGetSymbolAddress((void**)&wqkvl, g_wqkvl);
    cudaGetSymbolAddress((void**)&wo16,  g_wo16);
    cudaGetSymbolAddress((void**)&atth,  g_atth);
    cudaGetSymbolAddress((void**)&attl,  g_attl);

    cudaFuncSetAttribute(gemm_bf16x3,
                         cudaFuncAttributeMaxDynamicSharedMemorySize, GEMM_SMEM);
    cudaFuncSetAttribute(gemm_fp16x2,
                         cudaFuncAttributeMaxDynamicSharedMemorySize, GEMM2_SMEM);

    // splits for the QKV GEMM
    split_bf16<<<(BS_ * EMBED_ / 4 + 255) / 256, 256>>>(x, xh, xl, BS_ * EMBED_ / 4);
    split_bf16<<<(2048 * EMBED_ / 4 + 255) / 256, 256>>>(wq, wqkvh, wqkvl, 2048 * EMBED_ / 4);
    split_bf16<<<(512 * EMBED_ / 4 + 255) / 256, 256>>>(
        wk, wqkvh + (size_t)2048 * EMBED_, wqkvl + (size_t)2048 * EMBED_, 512 * EMBED_ / 4);
    split_bf16<<<(512 * EMBED_ / 4 + 255) / 256, 256>>>(
        wv, wqkvh + (size_t)2560 * EMBED_, wqkvl + (size_t)2560 * EMBED_, 512 * EMBED_ / 4);

    // fused QKV projection (bf16x3, R12 winner)
    gemm_bf16x3<<<dim3(NQKV_ / GN, BS_ / GM), 256, GEMM_SMEM>>>(
        xh, xl, wqkvh, wqkvl, qkvb, NQKV_);

    // K rmsnorm+rope, once (in place)
    norm_k<<<(BS_ * NKV_ * 32 + 255) / 256, 256>>>(qkvb, knw);

    // attention: fused q-norm/rope + sliding-window softmax + fp16 split out
    {
        size_t smem = (size_t)(2 * KMAX * KSTRIDE + KMAX) * sizeof(float);
        cudaFuncSetAttribute(attn_kernel,
                             cudaFuncAttributeMaxDynamicSharedMemorySize, (int)smem);
        dim3 grid(S_ / TQ, NH_, B_);
        attn_kernel<<<grid, 256, smem>>>(qkvb, amask, sinks, qnw, atth, attl);
    }

    // wo -> fp16, then O projection (fp16 2-pass)
    convert_fp16<<<(EMBED_ * EMBED_ / 4 + 255) / 256, 256>>>(wo, wo16, EMBED_ * EMBED_ / 4);
    gemm_fp16x2<<<dim3(EMBED_ / GN, BS_ / GM), 256, GEMM2_SMEM>>>(
        atth, attl, wo16, out, EMBED_);
}

// round 17
// speedup vs baseline: 1.8816x; 1.2059x over previous
#include <cuda_runtime.h>
#include <cuda_bf16.h>
#include <cuda_fp16.h>
#include <math.h>
#include <stdint.h>

// Problem constants
#define B_     2
#define S_     2048
#define EMBED_ 2048
#define NH_    32
#define NKV_   8
#define HD_    64
#define WIN_   128
#define BS_    (B_ * S_)      // 4096
#define NQKV_  3072           // 2048 q + 512 k + 512 v

// ---------------------------------------------------------------------------
// Scratch (device globals: no allocation allowed)
// ---------------------------------------------------------------------------
__device__ float   g_qkv [BS_ * NQKV_];        // fused qkv fp32
__device__ __half  g_xh  [BS_ * EMBED_];       // x hi (fp16)
__device__ __half  g_xl  [BS_ * EMBED_];       // x lo (fp16)
__device__ __half  g_wqkv16[NQKV_ * EMBED_];   // packed qkv weights, single fp16
__device__ __half  g_wo16[EMBED_ * EMBED_];    // O-proj weights, single fp16
__device__ __half  g_atth[BS_ * EMBED_];       // attention out, fp16 hi
__device__ __half  g_attl[BS_ * EMBED_];       // attention out, fp16 lo

// ---------------------------------------------------------------------------
// PTX helpers (portable sm_80+ features only: cp.async / ldmatrix / mma.sync)
// ---------------------------------------------------------------------------
__device__ __forceinline__ uint32_t smem_u32(const void* p) {
    uint32_t a;
    asm("{ .reg .u64 t; cvta.to.shared.u64 t, %1; cvt.u32.u64 %0, t; }"
        : "=r"(a) : "l"(p));
    return a;
}

#define CP_ASYNC16(sa, g) \
    asm volatile("cp.async.cg.shared.global [%0], [%1], 16;" \
                 :: "r"(sa), "l"(g) : "memory")
#define CP_COMMIT() asm volatile("cp.async.commit_group;" ::: "memory")
#define CP_WAIT(n)  asm volatile("cp.async.wait_group %0;" :: "n"(n) : "memory")

#define LDSM4(r0, r1, r2, r3, addr) \
    asm volatile("ldmatrix.sync.aligned.m8n8.x4.shared.b16 {%0,%1,%2,%3}, [%4];" \
                 : "=r"(r0), "=r"(r1), "=r"(r2), "=r"(r3) : "r"(addr))

#define MMA_FP16(c, a, b0, b1) \
    asm volatile("mma.sync.aligned.m16n8k16.row.col.f32.f16.f16.f32 " \
                 "{%0,%1,%2,%3}, {%4,%5,%6,%7}, {%8,%9}, {%0,%1,%2,%3};" \
                 : "+f"((c)[0]), "+f"((c)[1]), "+f"((c)[2]), "+f"((c)[3]) \
                 : "r"((a)[0]), "r"((a)[1]), "r"((a)[2]), "r"((a)[3]), \
                   "r"(b0), "r"(b1))

#define GM    128
#define GN    128
#define GK    32
#define NCH   (EMBED_ / GK)         // 64
#define MAT_BYTES   (128 * 64)      // 8192 (64B rows, no pad)

// 16B chunk c (0..3) of row r lives at swizzled position c ^ ((r>>1)&3)
__device__ __forceinline__ uint32_t swz(int row, int chunk) {
    return (uint32_t)(row * 64 + ((chunk ^ ((row >> 1) & 3)) << 4));
}

// ---------------------------------------------------------------------------
// fp16 2-pass NT GEMM: C[M,N] = (Ah+Al)[M,K] * W[N,K]^T, W single fp16.
// R14-validated structure: 128x128 tile, BK=32, 3-stage cp.async pipeline
// (one sync/iter), XOR-swizzled 64B rows, per-ntp single B LDSM,
// interleaved 2 MMAs per accumulator. 2 CTAs/SM (regs<=128, 72KB smem/CTA).
// Used for BOTH the QKV projection and the O projection.
// ---------------------------------------------------------------------------
#define STAGE2_BYTES (3 * MAT_BYTES)        // 24576: Ah, Al, W
#define GEMM2_SMEM   (3 * STAGE2_BYTES)     // 73728

__global__ void __launch_bounds__(256, 2)
gemm_fp16x2(const __half* __restrict__ Ah, const __half* __restrict__ Al,
            const __half* __restrict__ W, float* __restrict__ C, int N)
{
    extern __shared__ __align__(128) char sm[];
    const uint32_t smb = smem_u32(sm);

    const int tid  = threadIdx.x;
    const int warp = tid >> 5;
    const int lane = tid & 31;
    const int wm   = warp >> 1;
    const int wn   = warp & 1;

    const int m0 = blockIdx.y * GM;
    const int n0 = blockIdx.x * GN;

    const __half* src[3] = {
        Ah + (size_t)m0 * EMBED_, Al + (size_t)m0 * EMBED_,
        W  + (size_t)n0 * EMBED_
    };

    const int c0row = (tid * 2) >> 2,        c0c = (tid * 2) & 3;
    const int c1row = (tid * 2 + 1) >> 2,    c1c = (tid * 2 + 1) & 3;
    const uint32_t d0 = swz(c0row, c0c);
    const uint32_t d1 = swz(c1row, c1c);

#define ISSUE2(kt, sOffv) do {                                                 \
    const int _k0 = (kt) * GK;                                                 \
    const uint32_t _sb = smb + (sOffv);                                        \
    _Pragma("unroll")                                                          \
    for (int _m = 0; _m < 3; ++_m) {                                           \
        CP_ASYNC16(_sb + _m * MAT_BYTES + d0,                                  \
                   src[_m] + (size_t)c0row * EMBED_ + _k0 + c0c * 8);          \
        CP_ASYNC16(_sb + _m * MAT_BYTES + d1,                                  \
                   src[_m] + (size_t)c1row * EMBED_ + _k0 + c1c * 8);          \
    }                                                                          \
    CP_COMMIT();                                                               \
} while (0)

    float c[2][8][4];
#pragma unroll
    for (int t = 0; t < 2; t++)
#pragma unroll
        for (int nt = 0; nt < 8; nt++)
#pragma unroll
            for (int j = 0; j < 4; j++) c[t][nt][j] = 0.f;

    const int a_row  = wm * 32 + (lane & 15);
    const int a_cb   = lane >> 4;
    const int b_g8   = lane >> 3;
    const int b_row  = wn * 64 + ((b_g8 >> 1) ? 8 : 0) + (lane & 7);
    const int b_cb   = b_g8 & 1;

    ISSUE2(0, 0);
    ISSUE2(1, STAGE2_BYTES);

    uint32_t sOff = 0;
    uint32_t sNext2 = 2 * STAGE2_BYTES;

    for (int kt = 0; kt < NCH; ++kt) {
        if (kt + 1 < NCH) { CP_WAIT(1); }
        else              { CP_WAIT(0); }
        __syncthreads();

        if (kt + 2 < NCH) ISSUE2(kt + 2, sNext2);

        const uint32_t sb = smb + sOff;

#pragma unroll
        for (int kk = 0; kk < 2; ++kk) {
            uint32_t a[2][2][4];

#pragma unroll
            for (int hl = 0; hl < 2; ++hl)
#pragma unroll
                for (int t = 0; t < 2; ++t) {
                    int row = a_row + t * 16;
                    uint32_t ad = sb + hl * MAT_BYTES + swz(row, kk * 2 + a_cb);
                    LDSM4(a[hl][t][0], a[hl][t][1], a[hl][t][2], a[hl][t][3], ad);
                }

#pragma unroll
            for (int ntp = 0; ntp < 4; ++ntp) {
                uint32_t b[4];
                int row = b_row + ntp * 16;
                uint32_t bd = sb + 2 * MAT_BYTES + swz(row, kk * 2 + b_cb);
                LDSM4(b[0], b[1], b[2], b[3], bd);

#pragma unroll
                for (int t = 0; t < 2; ++t)
#pragma unroll
                    for (int half = 0; half < 2; ++half) {
                        float* cc = c[t][ntp * 2 + half];
                        MMA_FP16(cc, a[0][t], b[half * 2], b[half * 2 + 1]); // Ah*W
                        MMA_FP16(cc, a[1][t], b[half * 2], b[half * 2 + 1]); // Al*W
                    }
            }
        }

        sOff   = (sOff   == 2 * STAGE2_BYTES) ? 0 : sOff   + STAGE2_BYTES;
        sNext2 = (sNext2 == 2 * STAGE2_BYTES) ? 0 : sNext2 + STAGE2_BYTES;
    }

#pragma unroll
    for (int t = 0; t < 2; ++t) {
        const int r0 = m0 + wm * 32 + t * 16 + (lane >> 2);
#pragma unroll
        for (int nt = 0; nt < 8; ++nt) {
            const int col = n0 + wn * 64 + nt * 8 + (lane & 3) * 2;
            *(float2*)(C + (size_t)r0 * N + col)       = make_float2(c[t][nt][0], c[t][nt][1]);
            *(float2*)(C + (size_t)(r0 + 8) * N + col) = make_float2(c[t][nt][2], c[t][nt][3]);
        }
    }
#undef ISSUE2
}

// ---------------------------------------------------------------------------
// fp32 -> fp16 hi/lo split (vectorized by 4)
// ---------------------------------------------------------------------------
__global__ void split_fp16(const float* __restrict__ src,
                           __half* __restrict__ h, __half* __restrict__ l, int n4)
{
    int i = blockIdx.x * blockDim.x + threadIdx.x;
    if (i >= n4) return;
    float4 v = ((const float4*)src)[i];
    __half h0 = __float2half_rn(v.x);
    __half h1 = __float2half_rn(v.y);
    __half h2 = __float2half_rn(v.z);
    __half h3 = __float2half_rn(v.w);
    __half l0 = __float2half_rn(v.x - __half2float(h0));
    __half l1 = __float2half_rn(v.y - __half2float(h1));
    __half l2 = __float2half_rn(v.z - __half2float(h2));
    __half l3 = __float2half_rn(v.w - __half2float(h3));
    ((__half2*)h)[2 * i + 0] = __halves2half2(h0, h1);
    ((__half2*)h)[2 * i + 1] = __halves2half2(h2, h3);
    ((__half2*)l)[2 * i + 0] = __halves2half2(l0, l1);
    ((__half2*)l)[2 * i + 1] = __halves2half2(l2, l3);
}

// fp32 -> single fp16 convert (vectorized by 4)
__global__ void convert_fp16(const float* __restrict__ src,
                             __half* __restrict__ dst, int n4)
{
    int i = blockIdx.x * blockDim.x + threadIdx.x;
    if (i >= n4) return;
    float4 v = ((const float4*)src)[i];
    ((__half2*)dst)[2 * i + 0] = __floats2half2_rn(v.x, v.y);
    ((__half2*)dst)[2 * i + 1] = __floats2half2_rn(v.z, v.w);
}

#define LOG2_10000 13.28771237954945f

// ---------------------------------------------------------------------------
// In-place RMSNorm + RoPE of the K slice of the fused qkv buffer.
// ---------------------------------------------------------------------------
__global__ void norm_k(float* __restrict__ qkv, const float* __restrict__ knw)
{
    int wrp  = (blockIdx.x * blockDim.x + threadIdx.x) >> 5;
    int lane = threadIdx.x & 31;
    if (wrp >= BS_ * NKV_) return;

    int token = wrp >> 3;
    int head  = wrp & 7;
    int s     = token & (S_ - 1);

    float* p = qkv + (size_t)token * NQKV_ + 2048 + head * HD_;
    float t1 = p[lane];
    float t2 = p[lane + 32];

    float ss = t1 * t1 + t2 * t2;
#pragma unroll
    for (int o = 16; o; o >>= 1) ss += __shfl_xor_sync(0xffffffffu, ss, o);

    float inv = rsqrtf(ss * (1.0f / 64.0f) + 1e-6f);
    t1 = t1 * inv * knw[lane];
    t2 = t2 * inv * knw[lane + 32];

    float freq = exp2f(-LOG2_10000 * (float)lane * (1.0f / 32.0f));
    float ang  = (float)s * freq;
    float sn, cs;
    sincosf(ang, &sn, &cs);

    p[lane]      = t1 * cs - t2 * sn;
    p[lane + 32] = t2 * cs + t1 * sn;
}

// ---------------------------------------------------------------------------
// Sliding-window causal attention with sink. K pre-normed; Q normed/roped in
// registers. Epilogue writes fp16 hi/lo (feeds the fp16x2 O-projection).
// ---------------------------------------------------------------------------
#define TQ      64
#define KMAX    192
#define KSTRIDE 68

__global__ void __launch_bounds__(256, 2)
attn_kernel(const float* __restrict__ qkv, const int* __restrict__ mask,
            const float* __restrict__ sinks, const float* __restrict__ qnw,
            __half* __restrict__ outh, __half* __restrict__ outl)
{
    extern __shared__ float smf[];
    float* sK    = smf;
    float* sV    = smf + KMAX * KSTRIDE;
    float* sBias = smf + 2 * KMAX * KSTRIDE;

    const int b  = blockIdx.z;
    const int h  = blockIdx.y;
    const int q0 = blockIdx.x * TQ;
    const int kv = h >> 2;

    int kbase = q0 - (WIN_ - 1); if (kbase < 0) kbase = 0;
    const int nk = q0 + TQ - 1 - kbase + 1;

    for (int idx = threadIdx.x; idx < nk * 16; idx += blockDim.x) {
        int key = idx >> 4;
        int c4  = (idx & 15) << 2;
        size_t base = (size_t)(b * S_ + kbase + key) * NQKV_ + kv * HD_ + c4;
        float4 kr = *(const float4*)(qkv + base + 2048);
        float4 vr = *(const float4*)(qkv + base + 2560);
        *(float4*)(sK + key * KSTRIDE + c4) = kr;
        *(float4*)(sV + key * KSTRIDE + c4) = vr;
    }
    for (int idx = threadIdx.x; idx < nk; idx += blockDim.x)
        sBias[idx] = (mask[b * S_ + kbase + idx] > 0) ? 0.0f : -1e30f;
    __syncthreads();

    const int qloc = threadIdx.x >> 2;
    const int g    = threadIdx.x & 3;
    const int qg   = q0 + qloc;
    const int lane = threadIdx.x & 31;
    const unsigned gmask = 0xFu << (lane & ~3);

    float qr[16];
    const float* qp = qkv + (size_t)(b * S_ + qg) * NQKV_ + h * HD_;
#pragma unroll
    for (int i = 0; i < 8; i += 4) {
        float4 t = *(const float4*)(qp + g * 8 + i);
        qr[i] = t.x; qr[i+1] = t.y; qr[i+2] = t.z; qr[i+3] = t.w;
        float4 u = *(const float4*)(qp + 32 + g * 8 + i);
        qr[8+i] = u.x; qr[9+i] = u.y; qr[10+i] = u.z; qr[11+i] = u.w;
    }

    {
        float ss = 0.f;
#pragma unroll
        for (int i = 0; i < 16; i++) ss += qr[i] * qr[i];
        ss += __shfl_xor_sync(gmask, ss, 1);
        ss += __shfl_xor_sync(gmask, ss, 2);
        float inv = rsqrtf(ss * (1.0f / 64.0f) + 1e-6f);
#pragma unroll
        for (int i = 0; i < 8; i++) {
            qr[i]     *= inv * qnw[g * 8 + i];
            qr[i + 8] *= inv * qnw[32 + g * 8 + i];
        }
#pragma unroll
        for (int i = 0; i < 8; i++) {
            int d = g * 8 + i;
            float freq = exp2f(-LOG2_10000 * (float)d * (1.0f / 32.0f));
            float ang  = (float)qg * freq;
            float sn, cs;
            sincosf(ang, &sn, &cs);
            float t1 = qr[i], t2 = qr[i + 8];
            qr[i]     = t1 * cs - t2 * sn;
            qr[i + 8] = t2 * cs + t1 * sn;
        }
    }

    float m = sinks[h];
    float l = 1.0f;
    float acc[16];
#pragma unroll
    for (int i = 0; i < 16; i++) acc[i] = 0.f;

    int ks = qg - (WIN_ - 1); if (ks < 0) ks = 0;
    const float scale = 0.125f;

    for (int kk = ks; kk <= qg; kk++) {
        const int kl = kk - kbase;
        const float* kp = sK + kl * KSTRIDE;
        float s = 0.f;
#pragma unroll
        for (int i = 0; i < 8; i += 4) {
            float4 k4 = *(const float4*)(kp + g * 8 + i);
            s = fmaf(qr[i],   k4.x, s);
            s = fmaf(qr[i+1], k4.y, s);
            s = fmaf(qr[i+2], k4.z, s);
            s = fmaf(qr[i+3], k4.w, s);
            float4 k5 = *(const float4*)(kp + 32 + g * 8 + i);
            s = fmaf(qr[8+i],  k5.x, s);
            s = fmaf(qr[9+i],  k5.y, s);
            s = fmaf(qr[10+i], k5.z, s);
            s = fmaf(qr[11+i], k5.w, s);
        }
        s += __shfl_xor_sync(gmask, s, 1);
        s += __shfl_xor_sync(gmask, s, 2);
        s = s * scale + sBias[kl];

        float mnew = fmaxf(m, s);
        float corr = __expf(m - mnew);
        float p    = __expf(s - mnew);
        l = l * corr + p;
        m = mnew;

        const float* vp = sV + kl * KSTRIDE;
#pragma unroll
        for (int i = 0; i < 8; i += 4) {
            float4 v4 = *(const float4*)(vp + g * 8 + i);
            acc[i]   = acc[i]   * corr + p * v4.x;
            acc[i+1] = acc[i+1] * corr + p * v4.y;
            acc[i+2] = acc[i+2] * corr + p * v4.z;
            acc[i+3] = acc[i+3] * corr + p * v4.w;
            float4 v5 = *(const float4*)(vp + 32 + g * 8 + i);
            acc[8+i]  = acc[8+i]  * corr + p * v5.x;
            acc[9+i]  = acc[9+i]  * corr + p * v5.y;
            acc[10+i] = acc[10+i] * corr + p * v5.z;
            acc[11+i] = acc[11+i] * corr + p * v5.w;
        }
    }

    const float invl = 1.0f / l;
    size_t ob = (size_t)(b * S_ + qg) * EMBED_ + h * HD_ + g * 8;
#pragma unroll
    for (int seg = 0; seg < 2; seg++) {
        size_t o = ob + seg * 32;
        const float* a = acc + seg * 8;
#pragma unroll
        for (int i = 0; i < 8; i += 2) {
            float v0 = a[i] * invl, v1 = a[i+1] * invl;
            __half h0 = __float2half_rn(v0);
            __half h1 = __float2half_rn(v1);
            __half l0 = __float2half_rn(v0 - __half2float(h0));
            __half l1 = __float2half_rn(v1 - __half2float(h1));
            *(__half2*)(outh + o + i) = __halves2half2(h0, h1);
            *(__half2*)(outl + o + i) = __halves2half2(l0, l1);
        }
    }
}

// ---------------------------------------------------------------------------
// Launch
// ---------------------------------------------------------------------------
extern "C" void kernel_launch(void* const* d_in, const int* in_sizes, int n_in,
                              void* d_out, int out_size)
{
    const float* x      = (const float*)d_in[0];
    const int*   amask  = (const int*)d_in[1];
    const float* wq     = (const float*)d_in[2];
    const float* wk     = (const float*)d_in[3];
    const float* wv     = (const float*)d_in[4];
    const float* wo     = (const float*)d_in[5];
    const float* qnw    = (const float*)d_in[6];
    const float* knw    = (const float*)d_in[7];
    const float* sinks  = (const float*)d_in[8];
    float*       out    = (float*)d_out;

    float *qkvb;
    __half *xh, *xl, *wqkv16, *wo16, *atth, *attl;
    cudaGetSymbolAddress((void**)&qkvb,   g_qkv);
    cudaGetSymbolAddress((void**)&xh,     g_xh);
    cudaGetSymbolAddress((void**)&xl,     g_xl);
    cudaGetSymbolAddress((void**)&wqkv16, g_wqkv16);
    cudaGetSymbolAddress((void**)&wo16,   g_wo16);
    cudaGetSymbolAddress((void**)&atth,   g_atth);
    cudaGetSymbolAddress((void**)&attl,   g_attl);

    cudaFuncSetAttribute(gemm_fp16x2,
                         cudaFuncAttributeMaxDynamicSharedMemorySize, GEMM2_SMEM);

    // x -> fp16 hi/lo; packed qkv weights -> single fp16
    split_fp16<<<(BS_ * EMBED_ / 4 + 255) / 256, 256>>>(x, xh, xl, BS_ * EMBED_ / 4);
    convert_fp16<<<(2048 * EMBED_ / 4 + 255) / 256, 256>>>(wq, wqkv16, 2048 * EMBED_ / 4);
    convert_fp16<<<(512 * EMBED_ / 4 + 255) / 256, 256>>>(
        wk, wqkv16 + (size_t)2048 * EMBED_, 512 * EMBED_ / 4);
    convert_fp16<<<(512 * EMBED_ / 4 + 255) / 256, 256>>>(
        wv, wqkv16 + (size_t)2560 * EMBED_, 512 * EMBED_ / 4);

    // fused QKV projection (fp16 2-pass)
    gemm_fp16x2<<<dim3(NQKV_ / GN, BS_ / GM), 256, GEMM2_SMEM>>>(
        xh, xl, wqkv16, qkvb, NQKV_);

    // K rmsnorm+rope, once (in place)
    norm_k<<<(BS_ * NKV_ * 32 + 255) / 256, 256>>>(qkvb, knw);

    // attention: fused q-norm/rope + sliding-window softmax + fp16 split out
    {
        size_t smem = (size_t)(2 * KMAX * KSTRIDE + KMAX) * sizeof(float);
        cudaFuncSetAttribute(attn_kernel,
                             cudaFuncAttributeMaxDynamicSharedMemorySize, (int)smem);
        dim3 grid(S_ / TQ, NH_, B_);
        attn_kernel<<<grid, 256, smem>>>(qkvb, amask, sinks, qnw, atth, attl);
    }

    // wo -> fp16, then O projection (fp16 2-pass)
    convert_fp16<<<(EMBED_ * EMBED_ / 4 + 255) / 256, 256>>>(wo, wo16, EMBED_ * EMBED_ / 4);
    gemm_fp16x2<<<dim3(EMBED_ / GN, BS_ / GM), 256, GEMM2_SMEM>>>(
        atth, attl, wo16, out, EMBED_);
}